// round 14
// baseline (speedup 1.0000x reference)
#include <cuda_runtime.h>
#include <cuda_fp16.h>
#include <stdint.h>
#include <math.h>

#define Hdim 1024
#define Bdim 16
#define Sdim 256
#define Vdim 32000
#define G4H  4096
#define NTOK 4096
#define RNN_BLOCKS 128

// ---------------- scratch ----------------------------------------------------
__device__ float g_x   [(size_t)NTOK * Hdim];
__device__ float g_ih0 [(size_t)NTOK * G4H];
__device__ float g_proj[(size_t)NTOK * Hdim];
__device__ __align__(16) __half g_h0[2][Bdim][Hdim];
__device__ __align__(16) __half g_h1[2][Bdim][Hdim];
__device__ unsigned g_flags[RNN_BLOCKS * 32];   // one 128B line per flag
__device__ __align__(256) __half g_ah[(size_t)NTOK * Hdim];
__device__ __align__(256) __half g_bh[(size_t)Vdim * Hdim];
__device__ __align__(256) __half g_bl[(size_t)Vdim * Hdim];

// ---------------- helpers ----------------------------------------------------
__device__ __forceinline__ uint32_t smem_u32(const void* p){
    uint32_t a;
    asm("{ .reg .u64 t; cvta.to.shared.u64 t, %1; cvt.u32.u64 %0, t; }" : "=r"(a) : "l"(p));
    return a;
}
#define SWZ64(o) ((o) ^ (((o) >> 3) & 0x30))
__device__ __forceinline__ void cpa16(uint32_t dst, const void* src){
    asm volatile("cp.async.cg.shared.global [%0], [%1], 16;" :: "r"(dst), "l"(src) : "memory");
}
#define CPA_COMMIT() asm volatile("cp.async.commit_group;" ::: "memory")
__device__ __forceinline__ void ldsm4(uint32_t& r0, uint32_t& r1, uint32_t& r2, uint32_t& r3,
                                      uint32_t addr){
    asm volatile("ldmatrix.sync.aligned.m8n8.x4.shared.b16 {%0,%1,%2,%3}, [%4];"
                 : "=r"(r0), "=r"(r1), "=r"(r2), "=r"(r3) : "r"(addr));
}
__device__ __forceinline__ void ldsm2(uint32_t& r0, uint32_t& r1, uint32_t addr){
    asm volatile("ldmatrix.sync.aligned.m8n8.x2.shared.b16 {%0,%1}, [%2];"
                 : "=r"(r0), "=r"(r1) : "r"(addr));
}
__device__ __forceinline__ void mmah(float* d, uint32_t a0, uint32_t a1, uint32_t a2,
                                     uint32_t a3, uint32_t b0, uint32_t b1){
    asm volatile(
        "mma.sync.aligned.m16n8k16.row.col.f32.f16.f16.f32 "
        "{%0,%1,%2,%3}, {%4,%5,%6,%7}, {%8,%9}, {%0,%1,%2,%3};"
        : "+f"(d[0]), "+f"(d[1]), "+f"(d[2]), "+f"(d[3])
        : "r"(a0), "r"(a1), "r"(a2), "r"(a3), "r"(b0), "r"(b1));
}
__device__ __forceinline__ uint32_t pkh(float a, float b){
    __half2 h = __floats2half2_rn(a, b);
    return *(uint32_t*)&h;
}
__device__ __forceinline__ float sigmoidf_(float x){ return 1.0f / (1.0f + expf(-x)); }

// ---------------- embedding (writes fp32 x AND fp16 copy) ---------------------
__global__ void embed_kernel(const int* __restrict__ idx, const float* __restrict__ emb){
    int tok = blockIdx.x;
    int id  = idx[tok];
    float4 v = ((const float4*)(emb + (size_t)id * Hdim))[threadIdx.x];
    ((float4*)(g_x + (size_t)tok * Hdim))[threadIdx.x] = v;
    uint32_t* h2 = (uint32_t*)(g_ah + (size_t)tok * Hdim);
    h2[threadIdx.x * 2]     = pkh(v.x, v.y);
    h2[threadIdx.x * 2 + 1] = pkh(v.z, v.w);
}

// ---------------- fp32 -> fp16 (hi only) --------------------------------------
__global__ void half_kernel(const float* __restrict__ s, __half* __restrict__ h, size_t n4){
    size_t i = (size_t)blockIdx.x * blockDim.x + threadIdx.x;
    size_t st = (size_t)gridDim.x * blockDim.x;
    const float4* s4 = (const float4*)s;
    uint32_t* h2 = (uint32_t*)h;
    for (; i < n4; i += st){
        float4 v = s4[i];
        h2[i*2]   = pkh(v.x, v.y);
        h2[i*2+1] = pkh(v.z, v.w);
    }
}

// ---------------- fp32 -> (fp16 hi, fp16 lo), weights -------------------------
__global__ void split_kernel(const float* __restrict__ s, __half* __restrict__ h,
                             __half* __restrict__ l, size_t n4){
    size_t i = (size_t)blockIdx.x * blockDim.x + threadIdx.x;
    size_t st = (size_t)gridDim.x * blockDim.x;
    const float4* s4 = (const float4*)s;
    uint32_t* h2 = (uint32_t*)h;
    uint32_t* l2 = (uint32_t*)l;
    for (; i < n4; i += st){
        float4 v = s4[i];
        __half hx = __float2half_rn(v.x), hy = __float2half_rn(v.y);
        __half hz = __float2half_rn(v.z), hw = __float2half_rn(v.w);
        h2[i*2]   = pkh(__half2float(hx), __half2float(hy));
        h2[i*2+1] = pkh(__half2float(hz), __half2float(hw));
        l2[i*2]   = pkh(v.x - __half2float(hx), v.y - __half2float(hy));
        l2[i*2+1] = pkh(v.z - __half2float(hz), v.w - __half2float(hw));
    }
}

// ---------------- init --------------------------------------------------------
__global__ void init_kernel(){
    int i = blockIdx.x * blockDim.x + threadIdx.x;
    int st = gridDim.x * blockDim.x;
    uint32_t* p0 = (uint32_t*)g_h0;
    uint32_t* p1 = (uint32_t*)g_h1;
    for (int c = i; c < 16384; c += st){ p0[c] = 0u; p1[c] = 0u; }
    for (int c = i; c < RNN_BLOCKS * 32; c += st) g_flags[c] = 0u;
}

// ---------------- HMMA 2-pass fp16-split GEMM, 128x256 tile (ih / proj) -------
#define KC 32
#define STG 40960           // A 8K | Bh 16K | Bl 16K
#define GEMM_SMEM (4 * STG)

__global__ void __launch_bounds__(256, 1)
gemm_tc(const __half* __restrict__ Ah, const __half* __restrict__ Bh,
        const __half* __restrict__ Bl, const float* __restrict__ bias,
        float* __restrict__ C, int N){
    extern __shared__ __align__(1024) unsigned char dynsm[];
    uint32_t sb = smem_u32(dynsm);
    int tid = threadIdx.x, wid = tid >> 5, lane = tid & 31;
    int m0 = blockIdx.y * 128, n0 = blockIdx.x * 256;
    const int K = Hdim;
    int warp_m = (wid & 1) * 64, warp_n = (wid >> 1) * 64;

    float acc[4][8][4];
    #pragma unroll
    for (int mi = 0; mi < 4; mi++)
        #pragma unroll
        for (int nj = 0; nj < 8; nj++)
            #pragma unroll
            for (int q = 0; q < 4; q++) acc[mi][nj][q] = 0.0f;

    int srow0 = tid >> 2, sch0 = tid & 3;
    int srow1 = (tid + 256) >> 2, sch1 = (tid + 256) & 3;

    auto load_chunk = [&](int c, int s){
        int k0 = c * KC;
        uint32_t base = sb + s * STG;
        uint32_t d0 = SWZ64((uint32_t)(srow0 * 64 + sch0 * 16));
        uint32_t d1 = SWZ64((uint32_t)(srow1 * 64 + sch1 * 16));
        cpa16(base + d0, Ah + (size_t)(m0 + srow0) * K + k0 + sch0 * 8);
        cpa16(base + d1, Ah + (size_t)(m0 + srow1) * K + k0 + sch1 * 8);
        #pragma unroll
        for (int i = 0; i < 4; i++){
            int g = tid + i * 256;
            int row = g >> 2, ch = g & 3;
            uint32_t d = SWZ64((uint32_t)(row * 64 + ch * 16));
            cpa16(base +  8192 + d, Bh + (size_t)(n0 + row) * K + k0 + ch * 8);
            cpa16(base + 24576 + d, Bl + (size_t)(n0 + row) * K + k0 + ch * 8);
        }
        CPA_COMMIT();
    };

    const int NCH = K / KC;
    load_chunk(0, 0);
    load_chunk(1, 1);
    load_chunk(2, 2);

    int quad = lane >> 3, lr = lane & 7;
    int a_row = lr + (quad & 1) * 8;
    int a_chd = quad >> 1;
    int b_row = (quad >> 1) * 8 + lr;
    int b_chd = quad & 1;

    for (int c = 0; c < NCH; c++){
        int s = c & 3;
        if (c >= NCH - 3) asm volatile("cp.async.wait_group 0;" ::: "memory");
        else              asm volatile("cp.async.wait_group 2;" ::: "memory");
        __syncthreads();
        if (c + 3 < NCH) load_chunk(c + 3, (c + 3) & 3);

        uint32_t base = sb + s * STG;
        #pragma unroll
        for (int kk = 0; kk < 2; kk++){
            uint32_t ah[4][4];
            #pragma unroll
            for (int mi = 0; mi < 4; mi++){
                int row = warp_m + mi * 16 + a_row;
                int ch  = kk * 2 + a_chd;
                ldsm4(ah[mi][0], ah[mi][1], ah[mi][2], ah[mi][3],
                      base + SWZ64((uint32_t)(row * 64 + ch * 16)));
            }
            uint32_t bh[8][2], bl[8][2];
            #pragma unroll
            for (int p = 0; p < 4; p++){
                int row = warp_n + p * 16 + b_row;
                int ch  = kk * 2 + b_chd;
                ldsm4(bh[p*2][0], bh[p*2][1], bh[p*2+1][0], bh[p*2+1][1],
                      base +  8192 + SWZ64((uint32_t)(row * 64 + ch * 16)));
                ldsm4(bl[p*2][0], bl[p*2][1], bl[p*2+1][0], bl[p*2+1][1],
                      base + 24576 + SWZ64((uint32_t)(row * 64 + ch * 16)));
            }
            #pragma unroll
            for (int mi = 0; mi < 4; mi++)
                #pragma unroll
                for (int nj = 0; nj < 8; nj++){
                    mmah(acc[mi][nj], ah[mi][0], ah[mi][1], ah[mi][2], ah[mi][3],
                         bh[nj][0], bh[nj][1]);
                    mmah(acc[mi][nj], ah[mi][0], ah[mi][1], ah[mi][2], ah[mi][3],
                         bl[nj][0], bl[nj][1]);
                }
        }
        __syncthreads();
    }

    #pragma unroll
    for (int mi = 0; mi < 4; mi++){
        int rrow = m0 + warp_m + mi * 16 + (lane >> 2);
        #pragma unroll
        for (int nj = 0; nj < 8; nj++){
            int ccol = n0 + warp_n + nj * 8 + (lane & 3) * 2;
            float b0 = bias[ccol], b1 = bias[ccol + 1];
            float2 v0; v0.x = acc[mi][nj][0] + b0; v0.y = acc[mi][nj][1] + b1;
            float2 v1; v1.x = acc[mi][nj][2] + b0; v1.y = acc[mi][nj][3] + b1;
            *(float2*)(C + (size_t)rrow * N + ccol) = v0;
            *(float2*)(C + (size_t)(rrow + 8) * N + ccol) = v1;
        }
    }
}

// ---------------- HMMA single-pass fp16 GEMM, 128x256 tile (logits) -----------
#define STG1 24576            // A 8K | B 16K
#define GEMM1_SMEM (4 * STG1)

__global__ void __launch_bounds__(256, 1)
gemm_tc1(const __half* __restrict__ Ah, const __half* __restrict__ Bh,
         const float* __restrict__ bias, float* __restrict__ C, int N){
    extern __shared__ __align__(1024) unsigned char dynsm[];
    uint32_t sb = smem_u32(dynsm);
    int tid = threadIdx.x, wid = tid >> 5, lane = tid & 31;
    int m0 = blockIdx.y * 128, n0 = blockIdx.x * 256;
    const int K = Hdim;
    int warp_m = (wid & 1) * 64, warp_n = (wid >> 1) * 64;

    float acc[4][8][4];
    #pragma unroll
    for (int mi = 0; mi < 4; mi++)
        #pragma unroll
        for (int nj = 0; nj < 8; nj++)
            #pragma unroll
            for (int q = 0; q < 4; q++) acc[mi][nj][q] = 0.0f;

    int srow0 = tid >> 2, sch0 = tid & 3;
    int srow1 = (tid + 256) >> 2, sch1 = (tid + 256) & 3;

    auto load_chunk = [&](int c, int s){
        int k0 = c * KC;
        uint32_t base = sb + s * STG1;
        uint32_t d0 = SWZ64((uint32_t)(srow0 * 64 + sch0 * 16));
        uint32_t d1 = SWZ64((uint32_t)(srow1 * 64 + sch1 * 16));
        cpa16(base + d0, Ah + (size_t)(m0 + srow0) * K + k0 + sch0 * 8);
        cpa16(base + d1, Ah + (size_t)(m0 + srow1) * K + k0 + sch1 * 8);
        #pragma unroll
        for (int i = 0; i < 4; i++){
            int g = tid + i * 256;
            int row = g >> 2, ch = g & 3;
            uint32_t d = SWZ64((uint32_t)(row * 64 + ch * 16));
            cpa16(base + 8192 + d, Bh + (size_t)(n0 + row) * K + k0 + ch * 8);
        }
        CPA_COMMIT();
    };

    const int NCH = K / KC;
    load_chunk(0, 0);
    load_chunk(1, 1);
    load_chunk(2, 2);

    int quad = lane >> 3, lr = lane & 7;
    int a_row = lr + (quad & 1) * 8;
    int a_chd = quad >> 1;
    int b_row = (quad >> 1) * 8 + lr;
    int b_chd = quad & 1;

    for (int c = 0; c < NCH; c++){
        int s = c & 3;
        if (c >= NCH - 3) asm volatile("cp.async.wait_group 0;" ::: "memory");
        else              asm volatile("cp.async.wait_group 2;" ::: "memory");
        __syncthreads();
        if (c + 3 < NCH) load_chunk(c + 3, (c + 3) & 3);

        uint32_t base = sb + s * STG1;
        #pragma unroll
        for (int kk = 0; kk < 2; kk++){
            uint32_t ah[4][4];
            #pragma unroll
            for (int mi = 0; mi < 4; mi++){
                int row = warp_m + mi * 16 + a_row;
                int ch  = kk * 2 + a_chd;
                ldsm4(ah[mi][0], ah[mi][1], ah[mi][2], ah[mi][3],
                      base + SWZ64((uint32_t)(row * 64 + ch * 16)));
            }
            uint32_t bh[8][2];
            #pragma unroll
            for (int p = 0; p < 4; p++){
                int row = warp_n + p * 16 + b_row;
                int ch  = kk * 2 + b_chd;
                ldsm4(bh[p*2][0], bh[p*2][1], bh[p*2+1][0], bh[p*2+1][1],
                      base + 8192 + SWZ64((uint32_t)(row * 64 + ch * 16)));
            }
            #pragma unroll
            for (int mi = 0; mi < 4; mi++)
                #pragma unroll
                for (int nj = 0; nj < 8; nj++)
                    mmah(acc[mi][nj], ah[mi][0], ah[mi][1], ah[mi][2], ah[mi][3],
                         bh[nj][0], bh[nj][1]);
        }
        __syncthreads();
    }

    #pragma unroll
    for (int mi = 0; mi < 4; mi++){
        int rrow = m0 + warp_m + mi * 16 + (lane >> 2);
        #pragma unroll
        for (int nj = 0; nj < 8; nj++){
            int ccol = n0 + warp_n + nj * 8 + (lane & 3) * 2;
            float b0 = bias[ccol], b1 = bias[ccol + 1];
            float2 v0; v0.x = acc[mi][nj][0] + b0; v0.y = acc[mi][nj][1] + b1;
            float2 v1; v1.x = acc[mi][nj][2] + b0; v1.y = acc[mi][nj][3] + b1;
            *(float2*)(C + (size_t)rrow * N + ccol) = v0;
            *(float2*)(C + (size_t)(rrow + 8) * N + ccol) = v1;
        }
    }
}

// ---------------- persistent MMA sLSTM recurrence -----------------------------
#define W0OFF 0
#define W1OFF 65536
#define W2OFF 131072
#define BUFA  196608
#define BUFB  212992
#define RNN_SMEM 229376

// padded flag-array barrier: one 128B line per flag, 32-lane distributed poll
__device__ __forceinline__ void gridbar(int k){
    __syncthreads();
    unsigned tgt = (unsigned)k + 1u;
    if (threadIdx.x == 0)
        asm volatile("st.release.gpu.global.u32 [%0], %1;"
                     :: "l"(g_flags + blockIdx.x * 32), "r"(tgt) : "memory");
    if (threadIdx.x < 32){
        const unsigned* f = g_flags + threadIdx.x * 32;
        bool ok;
        do {
            unsigned v0, v1, v2, v3;
            asm volatile("ld.relaxed.gpu.global.u32 %0, [%1];" : "=r"(v0) : "l"(f)        : "memory");
            asm volatile("ld.relaxed.gpu.global.u32 %0, [%1];" : "=r"(v1) : "l"(f + 1024) : "memory");
            asm volatile("ld.relaxed.gpu.global.u32 %0, [%1];" : "=r"(v2) : "l"(f + 2048) : "memory");
            asm volatile("ld.relaxed.gpu.global.u32 %0, [%1];" : "=r"(v3) : "l"(f + 3072) : "memory");
            ok = (v0 >= tgt) && (v1 >= tgt) && (v2 >= tgt) && (v3 >= tgt);
        } while (!__all_sync(0xffffffffu, ok));
        __threadfence();
    }
    __syncthreads();
}

__global__ void __launch_bounds__(256, 1)
rnn_kernel(const float* __restrict__ Whh0, const float* __restrict__ Wih1,
           const float* __restrict__ Whh1, const float* __restrict__ bg1){
    extern __shared__ __align__(1024) unsigned char sm[];
    uint32_t sb = smem_u32(sm);
    float* gsc1 = (float*)(sm + BUFA);          // [64][16], overlays BUFA
    float* gsc2 = (float*)(sm + BUFA + 4096);   // [2][32][16]
    int tid = threadIdx.x, w = tid >> 5, lane = tid & 31;
    int j0 = blockIdx.x * 8;

    {
        const float* mats[3] = { Whh0, Wih1, Whh1 };
        for (int c = tid; c < 3 * 32 * 128; c += 256){
            int mat = c >> 12, cm = c & 4095;
            int r = cm >> 7, ch = cm & 127;
            int g = r >> 3, jj = r & 7;
            const float* src = mats[mat] + (size_t)(g * Hdim + j0 + jj) * Hdim + ch * 8;
            float4 v0 = *(const float4*)src;
            float4 v1 = *(const float4*)(src + 4);
            uint4 pk;
            pk.x = pkh(v0.x, v0.y); pk.y = pkh(v0.z, v0.w);
            pk.z = pkh(v1.x, v1.y); pk.w = pkh(v1.z, v1.w);
            *(uint4*)(sm + mat * 65536 + r * 2048 + (uint32_t)((ch ^ (r & 7)) << 4)) = pk;
        }
    }
    int jl = tid & 7, bbt = (tid >> 3) & 15, jg = j0 + jl;
    bool upd = tid < 128;
    float bg0 = 0, bg1v = 0, bg2 = 0, bg3 = 0;
    if (upd){
        bg0  = bg1[0 * Hdim + jg];
        bg1v = bg1[1 * Hdim + jg];
        bg2  = bg1[2 * Hdim + jg];
        bg3  = bg1[3 * Hdim + jg];
    }
    __syncthreads();

    int quad = lane >> 3, lr = lane & 7;
    int ar  = lr + (quad & 1) * 8;
    int ak8 = quad >> 1;
    int ar7 = ar & 7;
    int br  = lr;
    int bk8 = (lane >> 3) & 1;
    uint32_t wb1 = sb + ((w < 4) ? (uint32_t)(W0OFF + w * 8 * 2048)
                                 : (uint32_t)(W1OFF + (w - 4) * 8 * 2048)) + br * 2048;
    uint32_t wb2 = sb + W2OFF + (w & 3) * 8 * 2048 + br * 2048;
    int mb = lane >> 2, nn = (lane & 3) * 2;

    auto stage = [&](uint32_t buf, const char* hsrc, int hf){
        #pragma unroll
        for (int i = 0; i < 4; i++){
            int c = tid + i * 256;
            int b = c >> 6, ch = c & 63;
            cpa16(sb + buf + b * 1024 + (uint32_t)((ch ^ (b & 7)) << 4),
                  hsrc + b * 2048 + hf * 1024 + ch * 16);
        }
        CPA_COMMIT();
    };
    auto sweep1 = [&](uint32_t buf, int hf, float* a1){
        uint32_t ab = sb + buf + ar * 1024;
        #pragma unroll 8
        for (int ks = 0; ks < 32; ks++){
            uint32_t x0, x1, x2, x3, y0, y1;
            ldsm4(x0, x1, x2, x3, ab + (uint32_t)((((ks << 1) + ak8) ^ ar7) << 4));
            int kg = (hf << 5) + ks;
            ldsm2(y0, y1, wb1 + (uint32_t)((((kg << 1) + bk8) ^ br) << 4));
            mmah(a1, x0, x1, x2, x3, y0, y1);
        }
    };
    auto sweep2 = [&](uint32_t buf, int hf, float* a2){
        uint32_t ab = sb + buf + ar * 1024;
        int ks0 = (w >> 2) << 4;
        #pragma unroll 8
        for (int q = 0; q < 16; q++){
            int ks = ks0 + q;
            uint32_t x0, x1, x2, x3, y0, y1;
            ldsm4(x0, x1, x2, x3, ab + (uint32_t)((((ks << 1) + ak8) ^ ar7) << 4));
            int kg = (hf << 5) + ks;
            ldsm2(y0, y1, wb2 + (uint32_t)((((kg << 1) + bk8) ^ br) << 4));
            mmah(a2, x0, x1, x2, x3, y0, y1);
        }
    };

    float c0 = 0.0f, c1 = 0.0f;

    for (int k = 0; k <= Sdim; k++){
        float ihv0 = 0, ihv1 = 0, ihv2 = 0, ihv3 = 0;
        if (upd && k < Sdim){
            const float* ih = g_ih0 + (size_t)(bbt * Sdim + k) * G4H + jg;
            ihv0 = __ldg(ih);
            ihv1 = __ldg(ih + Hdim);
            ihv2 = __ldg(ih + 2 * Hdim);
            ihv3 = __ldg(ih + 3 * Hdim);
        }

        if (k >= 1){
            const char* h0src = (const char*)g_h0[(k - 1) & 1];
            const char* h1src = (const char*)g_h1[k & 1];
            float a1[4] = {0, 0, 0, 0}, a2[4] = {0, 0, 0, 0};

            stage(BUFA, h0src, 0);
            stage(BUFB, h0src, 1);
            asm volatile("cp.async.wait_group 1;" ::: "memory");
            __syncthreads();
            sweep1(BUFA, 0, a1);
            __syncthreads();
            stage(BUFA, h1src, 0);
            asm volatile("cp.async.wait_group 1;" ::: "memory");
            __syncthreads();
            sweep1(BUFB, 1, a1);
            __syncthreads();
            stage(BUFB, h1src, 1);
            asm volatile("cp.async.wait_group 1;" ::: "memory");
            __syncthreads();
            sweep2(BUFA, 0, a2);
            asm volatile("cp.async.wait_group 0;" ::: "memory");
            __syncthreads();               // BUFB visible + all BUFA reads done
            sweep2(BUFB, 1, a2);

            gsc1[(8 * w + nn) * 16 + mb]         = a1[0];
            gsc1[(8 * w + nn + 1) * 16 + mb]     = a1[1];
            gsc1[(8 * w + nn) * 16 + mb + 8]     = a1[2];
            gsc1[(8 * w + nn + 1) * 16 + mb + 8] = a1[3];
            float* g2 = gsc2 + (w >> 2) * 512;
            g2[(8 * (w & 3) + nn) * 16 + mb]         = a2[0];
            g2[(8 * (w & 3) + nn + 1) * 16 + mb]     = a2[1];
            g2[(8 * (w & 3) + nn) * 16 + mb + 8]     = a2[2];
            g2[(8 * (w & 3) + nn + 1) * 16 + mb + 8] = a2[3];
        }
        __syncthreads();

        if (upd){
            if (k < Sdim){
                float r0 = 0, r1 = 0, r2 = 0, r3 = 0;
                if (k >= 1){
                    r0 = gsc1[jl * 16 + bbt];
                    r1 = gsc1[(8 + jl) * 16 + bbt];
                    r2 = gsc1[(16 + jl) * 16 + bbt];
                    r3 = gsc1[(24 + jl) * 16 + bbt];
                }
                float gi = r0 + ihv0, gf = r1 + ihv1, gz = r2 + ihv2, go = r3 + ihv3;
                float cn = sigmoidf_(gf) * c0 + expf(gi) * tanhf(gz);
                float hn = sigmoidf_(go) * tanhf(cn);
                c0 = cn;
                g_h0[k & 1][bbt][jg] = __float2half_rn(hn);
            }
            if (k >= 1){
                float gi = gsc1[(32 + jl) * 16 + bbt] + gsc2[jl * 16 + bbt]
                         + gsc2[512 + jl * 16 + bbt] + bg0;
                float gf = gsc1[(40 + jl) * 16 + bbt] + gsc2[(8 + jl) * 16 + bbt]
                         + gsc2[512 + (8 + jl) * 16 + bbt] + bg1v;
                float gz = gsc1[(48 + jl) * 16 + bbt] + gsc2[(16 + jl) * 16 + bbt]
                         + gsc2[512 + (16 + jl) * 16 + bbt] + bg2;
                float go = gsc1[(56 + jl) * 16 + bbt] + gsc2[(24 + jl) * 16 + bbt]
                         + gsc2[512 + (24 + jl) * 16 + bbt] + bg3;
                float cn = sigmoidf_(gf) * c1 + expf(gi) * tanhf(gz);
                float hn = sigmoidf_(go) * tanhf(cn);
                c1 = cn;
                g_h1[(k - 1) & 1][bbt][jg] = __float2half_rn(hn);
                g_ah[((size_t)bbt * Sdim + (k - 1)) * Hdim + jg] = __float2half_rn(hn);
            }
        }
        if (k < Sdim) gridbar(k);
    }
}

// ---------------- GELU + residual + LayerNorm (emits fp32 + fp16) -------------
__global__ void __launch_bounds__(256)
post_kernel(const float* __restrict__ lng, const float* __restrict__ lnb){
    __shared__ float red[8];
    __shared__ float s_stat;
    int tok = blockIdx.x, tid = threadIdx.x;
    int lane = tid & 31, wid = tid >> 5;
    const float* pr = g_proj + (size_t)tok * Hdim;
    float* xr = g_x + (size_t)tok * Hdim;
    __half* hr = g_ah + (size_t)tok * Hdim;

    float yv[4];
    float lsum = 0.0f;
    #pragma unroll
    for (int i = 0; i < 4; i++){
        int e = tid + i * 256;
        float v = pr[e];
        float gl = 0.5f * v * (1.0f + erff(v * 0.70710678118654752440f));
        float y = gl + xr[e];
        yv[i] = y;
        lsum += y;
    }
    #pragma unroll
    for (int off = 16; off; off >>= 1) lsum += __shfl_xor_sync(0xffffffffu, lsum, off);
    if (lane == 0) red[wid] = lsum;
    __syncthreads();
    if (wid == 0){
        float ts = (lane < 8) ? red[lane] : 0.0f;
        #pragma unroll
        for (int off = 4; off; off >>= 1) ts += __shfl_xor_sync(0xffffffffu, ts, off);
        if (lane == 0) s_stat = ts * (1.0f / Hdim);
    }
    __syncthreads();
    float mean = s_stat;
    __syncthreads();

    float lss = 0.0f;
    #pragma unroll
    for (int i = 0; i < 4; i++){ float d = yv[i] - mean; lss += d * d; }
    #pragma unroll
    for (int off = 16; off; off >>= 1) lss += __shfl_xor_sync(0xffffffffu, lss, off);
    if (lane == 0) red[wid] = lss;
    __syncthreads();
    if (wid == 0){
        float ts = (lane < 8) ? red[lane] : 0.0f;
        #pragma unroll
        for (int off = 4; off; off >>= 1) ts += __shfl_xor_sync(0xffffffffu, ts, off);
        if (lane == 0) s_stat = rsqrtf(ts * (1.0f / Hdim) + 1e-5f);
    }
    __syncthreads();
    float inv = s_stat;

    #pragma unroll
    for (int i = 0; i < 4; i++){
        int e = tid + i * 256;
        float o = (yv[i] - mean) * inv * lng[e] + lnb[e];
        xr[e] = o;
        hr[e] = __float2half_rn(o);
    }
}

// ---------------- driver -------------------------------------------------------
extern "C" void kernel_launch(void* const* d_in, const int* in_sizes, int n_in,
                              void* d_out, int out_size){
    const int*   seq = (const int*)  d_in[0];
    const float* emb = (const float*)d_in[1];
    const float* Wih = (const float*)d_in[2];
    const float* Whh = (const float*)d_in[3];
    const float* bg  = (const float*)d_in[4];
    const float* pW  = (const float*)d_in[5];
    const float* pb  = (const float*)d_in[6];
    const float* lng = (const float*)d_in[7];
    const float* lnb = (const float*)d_in[8];
    const float* oW  = (const float*)d_in[9];
    const float* ob  = (const float*)d_in[10];
    float* out = (float*)d_out;

    cudaFuncSetAttribute(rnn_kernel, cudaFuncAttributeMaxDynamicSharedMemorySize, RNN_SMEM);
    cudaFuncSetAttribute(gemm_tc, cudaFuncAttributeMaxDynamicSharedMemorySize, GEMM_SMEM);
    cudaFuncSetAttribute(gemm_tc1, cudaFuncAttributeMaxDynamicSharedMemorySize, GEMM1_SMEM);

    float *px, *pih, *pproj;
    __half *pah, *pbh, *pbl;
    cudaGetSymbolAddress((void**)&px,    g_x);
    cudaGetSymbolAddress((void**)&pih,   g_ih0);
    cudaGetSymbolAddress((void**)&pproj, g_proj);
    cudaGetSymbolAddress((void**)&pah,   g_ah);
    cudaGetSymbolAddress((void**)&pbh,   g_bh);
    cudaGetSymbolAddress((void**)&pbl,   g_bl);

    embed_kernel<<<NTOK, 256>>>(seq, emb);

    for (int blk = 0; blk < 2; blk++){
        const float* Wih_b = Wih + (size_t)blk * 2 * G4H * Hdim;
        const float* Whh_b = Whh + (size_t)blk * 2 * G4H * Hdim;
        const float* bg_b  = bg  + blk * 2 * G4H;

        split_kernel<<<2048, 256>>>(Wih_b, pbh, pbl, (size_t)G4H * Hdim / 4);
        {
            dim3 g(G4H / 256, NTOK / 128);
            gemm_tc<<<g, 256, GEMM_SMEM>>>(pah, pbh, pbl, bg_b, pih, G4H);
        }

        init_kernel<<<64, 256>>>();
        rnn_kernel<<<RNN_BLOCKS, 256, RNN_SMEM>>>(
            Whh_b, Wih_b + (size_t)G4H * Hdim, Whh_b + (size_t)G4H * Hdim, bg_b + G4H);

        split_kernel<<<2048, 256>>>(pW + (size_t)blk * Hdim * Hdim, pbh, pbl,
                                    (size_t)Hdim * Hdim / 4);
        {
            dim3 g(Hdim / 256, NTOK / 128);
            gemm_tc<<<g, 256, GEMM_SMEM>>>(pah, pbh, pbl, pb + blk * Hdim, pproj, Hdim);
        }
        post_kernel<<<NTOK, 256>>>(lng + blk * Hdim, lnb + blk * Hdim);
    }

    // logits: single-pass fp16, 128x256 tile (terminal GEMM)
    half_kernel<<<2048, 256>>>(oW, pbh, (size_t)Vdim * Hdim / 4);
    {
        dim3 g(Vdim / 256, NTOK / 128);
        gemm_tc1<<<g, 256, GEMM1_SMEM>>>(pah, pbh, ob, out, Vdim);
    }
}

// round 15
// speedup vs baseline: 1.0354x; 1.0354x over previous
#include <cuda_runtime.h>
#include <cuda_fp16.h>
#include <stdint.h>
#include <math.h>

#define Hdim 1024
#define Bdim 16
#define Sdim 256
#define Vdim 32000
#define G4H  4096
#define NTOK 4096
#define RNN_BLOCKS 128

// ---------------- scratch ----------------------------------------------------
__device__ float g_x   [(size_t)NTOK * Hdim];
__device__ float g_ih0 [(size_t)NTOK * G4H];
__device__ float g_proj[(size_t)NTOK * Hdim];
__device__ __align__(16) __half g_h0[2][Bdim][Hdim];
__device__ __align__(16) __half g_h1[2][Bdim][Hdim];
__device__ unsigned g_flags[RNN_BLOCKS * 32];   // one 128B line per flag
__device__ __align__(256) __half g_ah[(size_t)NTOK * Hdim];
__device__ __align__(256) __half g_bh[(size_t)Vdim * Hdim];
__device__ __align__(256) __half g_bl[(size_t)Vdim * Hdim];

// ---------------- helpers ----------------------------------------------------
__device__ __forceinline__ uint32_t smem_u32(const void* p){
    uint32_t a;
    asm("{ .reg .u64 t; cvta.to.shared.u64 t, %1; cvt.u32.u64 %0, t; }" : "=r"(a) : "l"(p));
    return a;
}
#define SWZ64(o) ((o) ^ (((o) >> 3) & 0x30))
__device__ __forceinline__ void cpa16(uint32_t dst, const void* src){
    asm volatile("cp.async.cg.shared.global [%0], [%1], 16;" :: "r"(dst), "l"(src) : "memory");
}
#define CPA_COMMIT() asm volatile("cp.async.commit_group;" ::: "memory")
__device__ __forceinline__ void ldsm4(uint32_t& r0, uint32_t& r1, uint32_t& r2, uint32_t& r3,
                                      uint32_t addr){
    asm volatile("ldmatrix.sync.aligned.m8n8.x4.shared.b16 {%0,%1,%2,%3}, [%4];"
                 : "=r"(r0), "=r"(r1), "=r"(r2), "=r"(r3) : "r"(addr));
}
__device__ __forceinline__ void ldsm2(uint32_t& r0, uint32_t& r1, uint32_t addr){
    asm volatile("ldmatrix.sync.aligned.m8n8.x2.shared.b16 {%0,%1}, [%2];"
                 : "=r"(r0), "=r"(r1) : "r"(addr));
}
__device__ __forceinline__ void mmah(float* d, uint32_t a0, uint32_t a1, uint32_t a2,
                                     uint32_t a3, uint32_t b0, uint32_t b1){
    asm volatile(
        "mma.sync.aligned.m16n8k16.row.col.f32.f16.f16.f32 "
        "{%0,%1,%2,%3}, {%4,%5,%6,%7}, {%8,%9}, {%0,%1,%2,%3};"
        : "+f"(d[0]), "+f"(d[1]), "+f"(d[2]), "+f"(d[3])
        : "r"(a0), "r"(a1), "r"(a2), "r"(a3), "r"(b0), "r"(b1));
}
__device__ __forceinline__ uint32_t pkh(float a, float b){
    __half2 h = __floats2half2_rn(a, b);
    return *(uint32_t*)&h;
}
__device__ __forceinline__ float sigmoidf_(float x){ return 1.0f / (1.0f + expf(-x)); }

// ---------------- embedding (writes fp32 x AND fp16 copy) ---------------------
__global__ void embed_kernel(const int* __restrict__ idx, const float* __restrict__ emb){
    int tok = blockIdx.x;
    int id  = idx[tok];
    float4 v = ((const float4*)(emb + (size_t)id * Hdim))[threadIdx.x];
    ((float4*)(g_x + (size_t)tok * Hdim))[threadIdx.x] = v;
    uint32_t* h2 = (uint32_t*)(g_ah + (size_t)tok * Hdim);
    h2[threadIdx.x * 2]     = pkh(v.x, v.y);
    h2[threadIdx.x * 2 + 1] = pkh(v.z, v.w);
}

// ---------------- fp32 -> fp16 (hi only) --------------------------------------
__global__ void half_kernel(const float* __restrict__ s, __half* __restrict__ h, size_t n4){
    size_t i = (size_t)blockIdx.x * blockDim.x + threadIdx.x;
    size_t st = (size_t)gridDim.x * blockDim.x;
    const float4* s4 = (const float4*)s;
    uint32_t* h2 = (uint32_t*)h;
    for (; i < n4; i += st){
        float4 v = s4[i];
        h2[i*2]   = pkh(v.x, v.y);
        h2[i*2+1] = pkh(v.z, v.w);
    }
}

// ---------------- fp32 -> (fp16 hi, fp16 lo), weights -------------------------
__global__ void split_kernel(const float* __restrict__ s, __half* __restrict__ h,
                             __half* __restrict__ l, size_t n4){
    size_t i = (size_t)blockIdx.x * blockDim.x + threadIdx.x;
    size_t st = (size_t)gridDim.x * blockDim.x;
    const float4* s4 = (const float4*)s;
    uint32_t* h2 = (uint32_t*)h;
    uint32_t* l2 = (uint32_t*)l;
    for (; i < n4; i += st){
        float4 v = s4[i];
        __half hx = __float2half_rn(v.x), hy = __float2half_rn(v.y);
        __half hz = __float2half_rn(v.z), hw = __float2half_rn(v.w);
        h2[i*2]   = pkh(__half2float(hx), __half2float(hy));
        h2[i*2+1] = pkh(__half2float(hz), __half2float(hw));
        l2[i*2]   = pkh(v.x - __half2float(hx), v.y - __half2float(hy));
        l2[i*2+1] = pkh(v.z - __half2float(hz), v.w - __half2float(hw));
    }
}

// ---------------- init --------------------------------------------------------
__global__ void init_kernel(){
    int i = blockIdx.x * blockDim.x + threadIdx.x;
    int st = gridDim.x * blockDim.x;
    uint32_t* p0 = (uint32_t*)g_h0;
    uint32_t* p1 = (uint32_t*)g_h1;
    for (int c = i; c < 16384; c += st){ p0[c] = 0u; p1[c] = 0u; }
    for (int c = i; c < RNN_BLOCKS * 32; c += st) g_flags[c] = 0u;
}

// ---------------- HMMA 2-pass fp16-split GEMM, 128x128 tile (proj) ------------
#define KC 32
#define STG 24576
#define GEMM_SMEM (4 * STG)

__global__ void __launch_bounds__(256, 1)
gemm_tc(const __half* __restrict__ Ah, const __half* __restrict__ Bh,
        const __half* __restrict__ Bl, const float* __restrict__ bias,
        float* __restrict__ C, int N){
    extern __shared__ __align__(1024) unsigned char dynsm[];
    uint32_t sb = smem_u32(dynsm);
    int tid = threadIdx.x, wid = tid >> 5, lane = tid & 31;
    int m0 = blockIdx.y * 128, n0 = blockIdx.x * 128;
    const int K = Hdim;
    int warp_m = (wid & 1) * 64, warp_n = (wid >> 1) * 32;

    float acc[4][4][4];
    #pragma unroll
    for (int mi = 0; mi < 4; mi++)
        #pragma unroll
        for (int nj = 0; nj < 4; nj++)
            #pragma unroll
            for (int q = 0; q < 4; q++) acc[mi][nj][q] = 0.0f;

    int srow0 = tid >> 2,          sch0 = tid & 3;
    int srow1 = (tid + 256) >> 2,  sch1 = (tid + 256) & 3;

    auto load_chunk = [&](int c, int s){
        int k0 = c * KC;
        uint32_t base = sb + s * STG;
        uint32_t d0 = SWZ64((uint32_t)(srow0 * 64 + sch0 * 16));
        uint32_t d1 = SWZ64((uint32_t)(srow1 * 64 + sch1 * 16));
        cpa16(base +         d0, Ah + (size_t)(m0 + srow0) * K + k0 + sch0 * 8);
        cpa16(base +         d1, Ah + (size_t)(m0 + srow1) * K + k0 + sch1 * 8);
        cpa16(base +  8192 + d0, Bh + (size_t)(n0 + srow0) * K + k0 + sch0 * 8);
        cpa16(base +  8192 + d1, Bh + (size_t)(n0 + srow1) * K + k0 + sch1 * 8);
        cpa16(base + 16384 + d0, Bl + (size_t)(n0 + srow0) * K + k0 + sch0 * 8);
        cpa16(base + 16384 + d1, Bl + (size_t)(n0 + srow1) * K + k0 + sch1 * 8);
        CPA_COMMIT();
    };

    const int NCH = K / KC;
    load_chunk(0, 0);
    load_chunk(1, 1);
    load_chunk(2, 2);

    int quad = lane >> 3, lr = lane & 7;
    int a_row = lr + (quad & 1) * 8;
    int a_chd = quad >> 1;
    int b_row = (quad >> 1) * 8 + lr;
    int b_chd = quad & 1;

    for (int c = 0; c < NCH; c++){
        int s = c & 3;
        if (c >= NCH - 3) asm volatile("cp.async.wait_group 0;" ::: "memory");
        else              asm volatile("cp.async.wait_group 2;" ::: "memory");
        __syncthreads();
        if (c + 3 < NCH) load_chunk(c + 3, (c + 3) & 3);

        uint32_t base = sb + s * STG;
        #pragma unroll
        for (int kk = 0; kk < 2; kk++){
            uint32_t ah[4][4];
            #pragma unroll
            for (int mi = 0; mi < 4; mi++){
                int row = warp_m + mi * 16 + a_row;
                int ch  = kk * 2 + a_chd;
                ldsm4(ah[mi][0], ah[mi][1], ah[mi][2], ah[mi][3],
                      base + SWZ64((uint32_t)(row * 64 + ch * 16)));
            }
            uint32_t bh[4][2], bl[4][2];
            #pragma unroll
            for (int p = 0; p < 2; p++){
                int row = warp_n + p * 16 + b_row;
                int ch  = kk * 2 + b_chd;
                ldsm4(bh[p*2][0], bh[p*2][1], bh[p*2+1][0], bh[p*2+1][1],
                      base + 8192 + SWZ64((uint32_t)(row * 64 + ch * 16)));
                ldsm4(bl[p*2][0], bl[p*2][1], bl[p*2+1][0], bl[p*2+1][1],
                      base + 16384 + SWZ64((uint32_t)(row * 64 + ch * 16)));
            }
            #pragma unroll
            for (int mi = 0; mi < 4; mi++)
                #pragma unroll
                for (int nj = 0; nj < 4; nj++){
                    mmah(acc[mi][nj], ah[mi][0], ah[mi][1], ah[mi][2], ah[mi][3],
                         bh[nj][0], bh[nj][1]);
                    mmah(acc[mi][nj], ah[mi][0], ah[mi][1], ah[mi][2], ah[mi][3],
                         bl[nj][0], bl[nj][1]);
                }
        }
        __syncthreads();
    }

    #pragma unroll
    for (int mi = 0; mi < 4; mi++){
        int rrow = m0 + warp_m + mi * 16 + (lane >> 2);
        #pragma unroll
        for (int nj = 0; nj < 4; nj++){
            int ccol = n0 + warp_n + nj * 8 + (lane & 3) * 2;
            float b0 = bias[ccol], b1 = bias[ccol + 1];
            float2 v0; v0.x = acc[mi][nj][0] + b0; v0.y = acc[mi][nj][1] + b1;
            float2 v1; v1.x = acc[mi][nj][2] + b0; v1.y = acc[mi][nj][3] + b1;
            *(float2*)(C + (size_t)rrow * N + ccol) = v0;
            *(float2*)(C + (size_t)(rrow + 8) * N + ccol) = v1;
        }
    }
}

// ---------------- HMMA single-pass fp16 GEMM, 128x256 tile (ih / logits) ------
#define STG1 24576            // A 8K | B 16K
#define GEMM1_SMEM (4 * STG1)

__global__ void __launch_bounds__(256, 1)
gemm_tc1(const __half* __restrict__ Ah, const __half* __restrict__ Bh,
         const float* __restrict__ bias, float* __restrict__ C, int N){
    extern __shared__ __align__(1024) unsigned char dynsm[];
    uint32_t sb = smem_u32(dynsm);
    int tid = threadIdx.x, wid = tid >> 5, lane = tid & 31;
    int m0 = blockIdx.y * 128, n0 = blockIdx.x * 256;
    const int K = Hdim;
    int warp_m = (wid & 1) * 64, warp_n = (wid >> 1) * 64;

    float acc[4][8][4];
    #pragma unroll
    for (int mi = 0; mi < 4; mi++)
        #pragma unroll
        for (int nj = 0; nj < 8; nj++)
            #pragma unroll
            for (int q = 0; q < 4; q++) acc[mi][nj][q] = 0.0f;

    int srow0 = tid >> 2, sch0 = tid & 3;
    int srow1 = (tid + 256) >> 2, sch1 = (tid + 256) & 3;

    auto load_chunk = [&](int c, int s){
        int k0 = c * KC;
        uint32_t base = sb + s * STG1;
        uint32_t d0 = SWZ64((uint32_t)(srow0 * 64 + sch0 * 16));
        uint32_t d1 = SWZ64((uint32_t)(srow1 * 64 + sch1 * 16));
        cpa16(base + d0, Ah + (size_t)(m0 + srow0) * K + k0 + sch0 * 8);
        cpa16(base + d1, Ah + (size_t)(m0 + srow1) * K + k0 + sch1 * 8);
        #pragma unroll
        for (int i = 0; i < 4; i++){
            int g = tid + i * 256;
            int row = g >> 2, ch = g & 3;
            uint32_t d = SWZ64((uint32_t)(row * 64 + ch * 16));
            cpa16(base + 8192 + d, Bh + (size_t)(n0 + row) * K + k0 + ch * 8);
        }
        CPA_COMMIT();
    };

    const int NCH = K / KC;
    load_chunk(0, 0);
    load_chunk(1, 1);
    load_chunk(2, 2);

    int quad = lane >> 3, lr = lane & 7;
    int a_row = lr + (quad & 1) * 8;
    int a_chd = quad >> 1;
    int b_row = (quad >> 1) * 8 + lr;
    int b_chd = quad & 1;

    for (int c = 0; c < NCH; c++){
        int s = c & 3;
        if (c >= NCH - 3) asm volatile("cp.async.wait_group 0;" ::: "memory");
        else              asm volatile("cp.async.wait_group 2;" ::: "memory");
        __syncthreads();
        if (c + 3 < NCH) load_chunk(c + 3, (c + 3) & 3);

        uint32_t base = sb + s * STG1;
        #pragma unroll
        for (int kk = 0; kk < 2; kk++){
            uint32_t ah[4][4];
            #pragma unroll
            for (int mi = 0; mi < 4; mi++){
                int row = warp_m + mi * 16 + a_row;
                int ch  = kk * 2 + a_chd;
                ldsm4(ah[mi][0], ah[mi][1], ah[mi][2], ah[mi][3],
                      base + SWZ64((uint32_t)(row * 64 + ch * 16)));
            }
            uint32_t bh[8][2];
            #pragma unroll
            for (int p = 0; p < 4; p++){
                int row = warp_n + p * 16 + b_row;
                int ch  = kk * 2 + b_chd;
                ldsm4(bh[p*2][0], bh[p*2][1], bh[p*2+1][0], bh[p*2+1][1],
                      base + 8192 + SWZ64((uint32_t)(row * 64 + ch * 16)));
            }
            #pragma unroll
            for (int mi = 0; mi < 4; mi++)
                #pragma unroll
                for (int nj = 0; nj < 8; nj++)
                    mmah(acc[mi][nj], ah[mi][0], ah[mi][1], ah[mi][2], ah[mi][3],
                         bh[nj][0], bh[nj][1]);
        }
        __syncthreads();
    }

    #pragma unroll
    for (int mi = 0; mi < 4; mi++){
        int rrow = m0 + warp_m + mi * 16 + (lane >> 2);
        #pragma unroll
        for (int nj = 0; nj < 8; nj++){
            int ccol = n0 + warp_n + nj * 8 + (lane & 3) * 2;
            float b0 = bias[ccol], b1 = bias[ccol + 1];
            float2 v0; v0.x = acc[mi][nj][0] + b0; v0.y = acc[mi][nj][1] + b1;
            float2 v1; v1.x = acc[mi][nj][2] + b0; v1.y = acc[mi][nj][3] + b1;
            *(float2*)(C + (size_t)rrow * N + ccol) = v0;
            *(float2*)(C + (size_t)(rrow + 8) * N + ccol) = v1;
        }
    }
}

// ---------------- persistent MMA sLSTM recurrence -----------------------------
#define W0OFF 0
#define W1OFF 65536
#define W2OFF 131072
#define BUFA  196608
#define BUFB  212992
#define RNN_SMEM 229376

// padded flag-array barrier: one 128B line per flag, 32-lane distributed poll
__device__ __forceinline__ void gridbar(int k){
    __syncthreads();
    unsigned tgt = (unsigned)k + 1u;
    if (threadIdx.x == 0)
        asm volatile("st.release.gpu.global.u32 [%0], %1;"
                     :: "l"(g_flags + blockIdx.x * 32), "r"(tgt) : "memory");
    if (threadIdx.x < 32){
        const unsigned* f = g_flags + threadIdx.x * 32;
        bool ok;
        do {
            unsigned v0, v1, v2, v3;
            asm volatile("ld.relaxed.gpu.global.u32 %0, [%1];" : "=r"(v0) : "l"(f)        : "memory");
            asm volatile("ld.relaxed.gpu.global.u32 %0, [%1];" : "=r"(v1) : "l"(f + 1024) : "memory");
            asm volatile("ld.relaxed.gpu.global.u32 %0, [%1];" : "=r"(v2) : "l"(f + 2048) : "memory");
            asm volatile("ld.relaxed.gpu.global.u32 %0, [%1];" : "=r"(v3) : "l"(f + 3072) : "memory");
            ok = (v0 >= tgt) && (v1 >= tgt) && (v2 >= tgt) && (v3 >= tgt);
        } while (!__all_sync(0xffffffffu, ok));
        __threadfence();
    }
    __syncthreads();
}

__global__ void __launch_bounds__(256, 1)
rnn_kernel(const float* __restrict__ Whh0, const float* __restrict__ Wih1,
           const float* __restrict__ Whh1, const float* __restrict__ bg1){
    extern __shared__ __align__(1024) unsigned char sm[];
    uint32_t sb = smem_u32(sm);
    float* gsc1 = (float*)(sm + BUFA);          // [64][16], overlays BUFA
    float* gsc2 = (float*)(sm + BUFA + 4096);   // [2][32][16]
    int tid = threadIdx.x, w = tid >> 5, lane = tid & 31;
    int j0 = blockIdx.x * 8;

    {
        const float* mats[3] = { Whh0, Wih1, Whh1 };
        for (int c = tid; c < 3 * 32 * 128; c += 256){
            int mat = c >> 12, cm = c & 4095;
            int r = cm >> 7, ch = cm & 127;
            int g = r >> 3, jj = r & 7;
            const float* src = mats[mat] + (size_t)(g * Hdim + j0 + jj) * Hdim + ch * 8;
            float4 v0 = *(const float4*)src;
            float4 v1 = *(const float4*)(src + 4);
            uint4 pk;
            pk.x = pkh(v0.x, v0.y); pk.y = pkh(v0.z, v0.w);
            pk.z = pkh(v1.x, v1.y); pk.w = pkh(v1.z, v1.w);
            *(uint4*)(sm + mat * 65536 + r * 2048 + (uint32_t)((ch ^ (r & 7)) << 4)) = pk;
        }
    }
    int jl = tid & 7, bbt = (tid >> 3) & 15, jg = j0 + jl;
    bool upd = tid < 128;
    float bg0 = 0, bg1v = 0, bg2 = 0, bg3 = 0;
    if (upd){
        bg0  = bg1[0 * Hdim + jg];
        bg1v = bg1[1 * Hdim + jg];
        bg2  = bg1[2 * Hdim + jg];
        bg3  = bg1[3 * Hdim + jg];
    }
    __syncthreads();

    int quad = lane >> 3, lr = lane & 7;
    int ar  = lr + (quad & 1) * 8;
    int ak8 = quad >> 1;
    int ar7 = ar & 7;
    int br  = lr;
    int bk8 = (lane >> 3) & 1;
    uint32_t wb1 = sb + ((w < 4) ? (uint32_t)(W0OFF + w * 8 * 2048)
                                 : (uint32_t)(W1OFF + (w - 4) * 8 * 2048)) + br * 2048;
    uint32_t wb2 = sb + W2OFF + (w & 3) * 8 * 2048 + br * 2048;
    int mb = lane >> 2, nn = (lane & 3) * 2;

    auto stage = [&](uint32_t buf, const char* hsrc, int hf){
        #pragma unroll
        for (int i = 0; i < 4; i++){
            int c = tid + i * 256;
            int b = c >> 6, ch = c & 63;
            cpa16(sb + buf + b * 1024 + (uint32_t)((ch ^ (b & 7)) << 4),
                  hsrc + b * 2048 + hf * 1024 + ch * 16);
        }
        CPA_COMMIT();
    };
    auto sweep1 = [&](uint32_t buf, int hf, float* a1){
        uint32_t ab = sb + buf + ar * 1024;
        #pragma unroll 8
        for (int ks = 0; ks < 32; ks++){
            uint32_t x0, x1, x2, x3, y0, y1;
            ldsm4(x0, x1, x2, x3, ab + (uint32_t)((((ks << 1) + ak8) ^ ar7) << 4));
            int kg = (hf << 5) + ks;
            ldsm2(y0, y1, wb1 + (uint32_t)((((kg << 1) + bk8) ^ br) << 4));
            mmah(a1, x0, x1, x2, x3, y0, y1);
        }
    };
    auto sweep2 = [&](uint32_t buf, int hf, float* a2){
        uint32_t ab = sb + buf + ar * 1024;
        int ks0 = (w >> 2) << 4;
        #pragma unroll 8
        for (int q = 0; q < 16; q++){
            int ks = ks0 + q;
            uint32_t x0, x1, x2, x3, y0, y1;
            ldsm4(x0, x1, x2, x3, ab + (uint32_t)((((ks << 1) + ak8) ^ ar7) << 4));
            int kg = (hf << 5) + ks;
            ldsm2(y0, y1, wb2 + (uint32_t)((((kg << 1) + bk8) ^ br) << 4));
            mmah(a2, x0, x1, x2, x3, y0, y1);
        }
    };

    float c0 = 0.0f, c1 = 0.0f;

    for (int k = 0; k <= Sdim; k++){
        float ihv0 = 0, ihv1 = 0, ihv2 = 0, ihv3 = 0;
        if (upd && k < Sdim){
            const float* ih = g_ih0 + (size_t)(bbt * Sdim + k) * G4H + jg;
            ihv0 = __ldg(ih);
            ihv1 = __ldg(ih + Hdim);
            ihv2 = __ldg(ih + 2 * Hdim);
            ihv3 = __ldg(ih + 3 * Hdim);
        }

        if (k >= 1){
            const char* h0src = (const char*)g_h0[(k - 1) & 1];
            const char* h1src = (const char*)g_h1[k & 1];
            float a1[4] = {0, 0, 0, 0}, a2[4] = {0, 0, 0, 0};

            stage(BUFA, h0src, 0);
            stage(BUFB, h0src, 1);
            asm volatile("cp.async.wait_group 1;" ::: "memory");
            __syncthreads();
            sweep1(BUFA, 0, a1);
            __syncthreads();
            stage(BUFA, h1src, 0);
            asm volatile("cp.async.wait_group 1;" ::: "memory");
            __syncthreads();
            sweep1(BUFB, 1, a1);
            __syncthreads();
            stage(BUFB, h1src, 1);
            asm volatile("cp.async.wait_group 1;" ::: "memory");
            __syncthreads();
            sweep2(BUFA, 0, a2);
            asm volatile("cp.async.wait_group 0;" ::: "memory");
            __syncthreads();               // BUFB visible + all BUFA reads done
            sweep2(BUFB, 1, a2);

            gsc1[(8 * w + nn) * 16 + mb]         = a1[0];
            gsc1[(8 * w + nn + 1) * 16 + mb]     = a1[1];
            gsc1[(8 * w + nn) * 16 + mb + 8]     = a1[2];
            gsc1[(8 * w + nn + 1) * 16 + mb + 8] = a1[3];
            float* g2 = gsc2 + (w >> 2) * 512;
            g2[(8 * (w & 3) + nn) * 16 + mb]         = a2[0];
            g2[(8 * (w & 3) + nn + 1) * 16 + mb]     = a2[1];
            g2[(8 * (w & 3) + nn) * 16 + mb + 8]     = a2[2];
            g2[(8 * (w & 3) + nn + 1) * 16 + mb + 8] = a2[3];
        }
        __syncthreads();

        if (upd){
            if (k < Sdim){
                float r0 = 0, r1 = 0, r2 = 0, r3 = 0;
                if (k >= 1){
                    r0 = gsc1[jl * 16 + bbt];
                    r1 = gsc1[(8 + jl) * 16 + bbt];
                    r2 = gsc1[(16 + jl) * 16 + bbt];
                    r3 = gsc1[(24 + jl) * 16 + bbt];
                }
                float gi = r0 + ihv0, gf = r1 + ihv1, gz = r2 + ihv2, go = r3 + ihv3;
                float cn = sigmoidf_(gf) * c0 + expf(gi) * tanhf(gz);
                float hn = sigmoidf_(go) * tanhf(cn);
                c0 = cn;
                g_h0[k & 1][bbt][jg] = __float2half_rn(hn);
            }
            if (k >= 1){
                float gi = gsc1[(32 + jl) * 16 + bbt] + gsc2[jl * 16 + bbt]
                         + gsc2[512 + jl * 16 + bbt] + bg0;
                float gf = gsc1[(40 + jl) * 16 + bbt] + gsc2[(8 + jl) * 16 + bbt]
                         + gsc2[512 + (8 + jl) * 16 + bbt] + bg1v;
                float gz = gsc1[(48 + jl) * 16 + bbt] + gsc2[(16 + jl) * 16 + bbt]
                         + gsc2[512 + (16 + jl) * 16 + bbt] + bg2;
                float go = gsc1[(56 + jl) * 16 + bbt] + gsc2[(24 + jl) * 16 + bbt]
                         + gsc2[512 + (24 + jl) * 16 + bbt] + bg3;
                float cn = sigmoidf_(gf) * c1 + expf(gi) * tanhf(gz);
                float hn = sigmoidf_(go) * tanhf(cn);
                c1 = cn;
                g_h1[(k - 1) & 1][bbt][jg] = __float2half_rn(hn);
                g_ah[((size_t)bbt * Sdim + (k - 1)) * Hdim + jg] = __float2half_rn(hn);
            }
        }
        if (k < Sdim) gridbar(k);
    }
}

// ---------------- GELU + residual + LayerNorm (emits fp32 + fp16) -------------
__global__ void __launch_bounds__(256)
post_kernel(const float* __restrict__ lng, const float* __restrict__ lnb){
    __shared__ float red[8];
    __shared__ float s_stat;
    int tok = blockIdx.x, tid = threadIdx.x;
    int lane = tid & 31, wid = tid >> 5;
    const float* pr = g_proj + (size_t)tok * Hdim;
    float* xr = g_x + (size_t)tok * Hdim;
    __half* hr = g_ah + (size_t)tok * Hdim;

    float yv[4];
    float lsum = 0.0f;
    #pragma unroll
    for (int i = 0; i < 4; i++){
        int e = tid + i * 256;
        float v = pr[e];
        float gl = 0.5f * v * (1.0f + erff(v * 0.70710678118654752440f));
        float y = gl + xr[e];
        yv[i] = y;
        lsum += y;
    }
    #pragma unroll
    for (int off = 16; off; off >>= 1) lsum += __shfl_xor_sync(0xffffffffu, lsum, off);
    if (lane == 0) red[wid] = lsum;
    __syncthreads();
    if (wid == 0){
        float ts = (lane < 8) ? red[lane] : 0.0f;
        #pragma unroll
        for (int off = 4; off; off >>= 1) ts += __shfl_xor_sync(0xffffffffu, ts, off);
        if (lane == 0) s_stat = ts * (1.0f / Hdim);
    }
    __syncthreads();
    float mean = s_stat;
    __syncthreads();

    float lss = 0.0f;
    #pragma unroll
    for (int i = 0; i < 4; i++){ float d = yv[i] - mean; lss += d * d; }
    #pragma unroll
    for (int off = 16; off; off >>= 1) lss += __shfl_xor_sync(0xffffffffu, lss, off);
    if (lane == 0) red[wid] = lss;
    __syncthreads();
    if (wid == 0){
        float ts = (lane < 8) ? red[lane] : 0.0f;
        #pragma unroll
        for (int off = 4; off; off >>= 1) ts += __shfl_xor_sync(0xffffffffu, ts, off);
        if (lane == 0) s_stat = rsqrtf(ts * (1.0f / Hdim) + 1e-5f);
    }
    __syncthreads();
    float inv = s_stat;

    #pragma unroll
    for (int i = 0; i < 4; i++){
        int e = tid + i * 256;
        float o = (yv[i] - mean) * inv * lng[e] + lnb[e];
        xr[e] = o;
        hr[e] = __float2half_rn(o);
    }
}

// ---------------- driver -------------------------------------------------------
extern "C" void kernel_launch(void* const* d_in, const int* in_sizes, int n_in,
                              void* d_out, int out_size){
    const int*   seq = (const int*)  d_in[0];
    const float* emb = (const float*)d_in[1];
    const float* Wih = (const float*)d_in[2];
    const float* Whh = (const float*)d_in[3];
    const float* bg  = (const float*)d_in[4];
    const float* pW  = (const float*)d_in[5];
    const float* pb  = (const float*)d_in[6];
    const float* lng = (const float*)d_in[7];
    const float* lnb = (const float*)d_in[8];
    const float* oW  = (const float*)d_in[9];
    const float* ob  = (const float*)d_in[10];
    float* out = (float*)d_out;

    cudaFuncSetAttribute(rnn_kernel, cudaFuncAttributeMaxDynamicSharedMemorySize, RNN_SMEM);
    cudaFuncSetAttribute(gemm_tc, cudaFuncAttributeMaxDynamicSharedMemorySize, GEMM_SMEM);
    cudaFuncSetAttribute(gemm_tc1, cudaFuncAttributeMaxDynamicSharedMemorySize, GEMM1_SMEM);

    float *px, *pih, *pproj;
    __half *pah, *pbh, *pbl;
    cudaGetSymbolAddress((void**)&px,    g_x);
    cudaGetSymbolAddress((void**)&pih,   g_ih0);
    cudaGetSymbolAddress((void**)&pproj, g_proj);
    cudaGetSymbolAddress((void**)&pah,   g_ah);
    cudaGetSymbolAddress((void**)&pbh,   g_bh);
    cudaGetSymbolAddress((void**)&pbl,   g_bl);

    embed_kernel<<<NTOK, 256>>>(seq, emb);

    for (int blk = 0; blk < 2; blk++){
        const float* Wih_b = Wih + (size_t)blk * 2 * G4H * Hdim;
        const float* Whh_b = Whh + (size_t)blk * 2 * G4H * Hdim;
        const float* bg_b  = bg  + blk * 2 * G4H;

        // ih0: single-pass fp16 (Wih rounding uncompensated; error budget OK)
        half_kernel<<<2048, 256>>>(Wih_b, pbh, (size_t)G4H * Hdim / 4);
        {
            dim3 g(G4H / 256, NTOK / 128);
            gemm_tc1<<<g, 256, GEMM1_SMEM>>>(pah, pbh, bg_b, pih, G4H);
        }

        init_kernel<<<64, 256>>>();
        rnn_kernel<<<RNN_BLOCKS, 256, RNN_SMEM>>>(
            Whh_b, Wih_b + (size_t)G4H * Hdim, Whh_b + (size_t)G4H * Hdim, bg_b + G4H);

        // proj: 2-pass compensated (cheap; keeps accuracy headroom)
        split_kernel<<<2048, 256>>>(pW + (size_t)blk * Hdim * Hdim, pbh, pbl,
                                    (size_t)Hdim * Hdim / 4);
        {
            dim3 g(Hdim / 128, NTOK / 128);
            gemm_tc<<<g, 256, GEMM_SMEM>>>(pah, pbh, pbl, pb + blk * Hdim, pproj, Hdim);
        }
        post_kernel<<<NTOK, 256>>>(lng + blk * Hdim, lnb + blk * Hdim);
    }

    // logits: single-pass fp16, 128x256 tile (terminal GEMM)
    half_kernel<<<2048, 256>>>(oW, pbh, (size_t)Vdim * Hdim / 4);
    {
        dim3 g(Vdim / 256, NTOK / 128);
        gemm_tc1<<<g, 256, GEMM1_SMEM>>>(pah, pbh, ob, out, Vdim);
    }
}

// round 17
// speedup vs baseline: 1.0530x; 1.0170x over previous
#include <cuda_runtime.h>
#include <cuda_fp16.h>
#include <stdint.h>
#include <math.h>

#define Hdim 1024
#define Bdim 16
#define Sdim 256
#define Vdim 32000
#define G4H  4096
#define NTOK 4096
#define RNN_BLOCKS 128

// ---------------- scratch ----------------------------------------------------
__device__ float g_x   [(size_t)NTOK * Hdim];
__device__ float g_ih0 [(size_t)NTOK * G4H];
__device__ float g_proj[(size_t)NTOK * Hdim];
__device__ __align__(16) __half g_h0[2][Bdim][Hdim];
__device__ __align__(16) __half g_h1[2][Bdim][Hdim];
__device__ unsigned g_flags[RNN_BLOCKS * 32];   // one 128B line per flag
__device__ __align__(256) __half g_ah[(size_t)NTOK * Hdim];
__device__ __align__(256) __half g_bh[(size_t)Vdim * Hdim];

// ---------------- helpers ----------------------------------------------------
__device__ __forceinline__ uint32_t smem_u32(const void* p){
    uint32_t a;
    asm("{ .reg .u64 t; cvta.to.shared.u64 t, %1; cvt.u32.u64 %0, t; }" : "=r"(a) : "l"(p));
    return a;
}
#define SWZ64(o) ((o) ^ (((o) >> 3) & 0x30))
__device__ __forceinline__ void cpa16(uint32_t dst, const void* src){
    asm volatile("cp.async.cg.shared.global [%0], [%1], 16;" :: "r"(dst), "l"(src) : "memory");
}
#define CPA_COMMIT() asm volatile("cp.async.commit_group;" ::: "memory")
__device__ __forceinline__ void ldsm4(uint32_t& r0, uint32_t& r1, uint32_t& r2, uint32_t& r3,
                                      uint32_t addr){
    asm volatile("ldmatrix.sync.aligned.m8n8.x4.shared.b16 {%0,%1,%2,%3}, [%4];"
                 : "=r"(r0), "=r"(r1), "=r"(r2), "=r"(r3) : "r"(addr));
}
__device__ __forceinline__ void ldsm2(uint32_t& r0, uint32_t& r1, uint32_t addr){
    asm volatile("ldmatrix.sync.aligned.m8n8.x2.shared.b16 {%0,%1}, [%2];"
                 : "=r"(r0), "=r"(r1) : "r"(addr));
}
__device__ __forceinline__ void mmah(float* d, uint32_t a0, uint32_t a1, uint32_t a2,
                                     uint32_t a3, uint32_t b0, uint32_t b1){
    asm volatile(
        "mma.sync.aligned.m16n8k16.row.col.f32.f16.f16.f32 "
        "{%0,%1,%2,%3}, {%4,%5,%6,%7}, {%8,%9}, {%0,%1,%2,%3};"
        : "+f"(d[0]), "+f"(d[1]), "+f"(d[2]), "+f"(d[3])
        : "r"(a0), "r"(a1), "r"(a2), "r"(a3), "r"(b0), "r"(b1));
}
__device__ __forceinline__ uint32_t pkh(float a, float b){
    __half2 h = __floats2half2_rn(a, b);
    return *(uint32_t*)&h;
}
__device__ __forceinline__ float sigmoidf_(float x){ return 1.0f / (1.0f + expf(-x)); }

// ---------------- embedding (writes fp32 x AND fp16 copy) ---------------------
__global__ void embed_kernel(const int* __restrict__ idx, const float* __restrict__ emb){
    int tok = blockIdx.x;
    int id  = idx[tok];
    float4 v = ((const float4*)(emb + (size_t)id * Hdim))[threadIdx.x];
    ((float4*)(g_x + (size_t)tok * Hdim))[threadIdx.x] = v;
    uint32_t* h2 = (uint32_t*)(g_ah + (size_t)tok * Hdim);
    h2[threadIdx.x * 2]     = pkh(v.x, v.y);
    h2[threadIdx.x * 2 + 1] = pkh(v.z, v.w);
}

// ---------------- fp32 -> fp16 (hi only) --------------------------------------
__global__ void half_kernel(const float* __restrict__ s, __half* __restrict__ h, size_t n4){
    size_t i = (size_t)blockIdx.x * blockDim.x + threadIdx.x;
    size_t st = (size_t)gridDim.x * blockDim.x;
    const float4* s4 = (const float4*)s;
    uint32_t* h2 = (uint32_t*)h;
    for (; i < n4; i += st){
        float4 v = s4[i];
        h2[i*2]   = pkh(v.x, v.y);
        h2[i*2+1] = pkh(v.z, v.w);
    }
}

// ---------------- init --------------------------------------------------------
__global__ void init_kernel(){
    int i = blockIdx.x * blockDim.x + threadIdx.x;
    int st = gridDim.x * blockDim.x;
    uint32_t* p0 = (uint32_t*)g_h0;
    uint32_t* p1 = (uint32_t*)g_h1;
    for (int c = i; c < 16384; c += st){ p0[c] = 0u; p1[c] = 0u; }
    for (int c = i; c < RNN_BLOCKS * 32; c += st) g_flags[c] = 0u;
}

// ---------------- HMMA single-pass fp16 GEMM, 128x256 tile --------------------
// Grid is M-MAJOR: blockIdx.x = m-tile, blockIdx.y = n-tile. A wave of CTAs
// covers all m-tiles of a few n-tiles -> A stays L2-resident, B read ~once.
#define KC 32
#define STG1 24576            // A 8K | B 16K
#define GEMM1_SMEM (4 * STG1)

__global__ void __launch_bounds__(256, 1)
gemm_tc1(const __half* __restrict__ Ah, const __half* __restrict__ Bh,
         const float* __restrict__ bias, float* __restrict__ C, int N){
    extern __shared__ __align__(1024) unsigned char dynsm[];
    uint32_t sb = smem_u32(dynsm);
    int tid = threadIdx.x, wid = tid >> 5, lane = tid & 31;
    int m0 = blockIdx.x * 128, n0 = blockIdx.y * 256;
    const int K = Hdim;
    int warp_m = (wid & 1) * 64, warp_n = (wid >> 1) * 64;

    float acc[4][8][4];
    #pragma unroll
    for (int mi = 0; mi < 4; mi++)
        #pragma unroll
        for (int nj = 0; nj < 8; nj++)
            #pragma unroll
            for (int q = 0; q < 4; q++) acc[mi][nj][q] = 0.0f;

    int srow0 = tid >> 2, sch0 = tid & 3;
    int srow1 = (tid + 256) >> 2, sch1 = (tid + 256) & 3;

    auto load_chunk = [&](int c, int s){
        int k0 = c * KC;
        uint32_t base = sb + s * STG1;
        uint32_t d0 = SWZ64((uint32_t)(srow0 * 64 + sch0 * 16));
        uint32_t d1 = SWZ64((uint32_t)(srow1 * 64 + sch1 * 16));
        cpa16(base + d0, Ah + (size_t)(m0 + srow0) * K + k0 + sch0 * 8);
        cpa16(base + d1, Ah + (size_t)(m0 + srow1) * K + k0 + sch1 * 8);
        #pragma unroll
        for (int i = 0; i < 4; i++){
            int g = tid + i * 256;
            int row = g >> 2, ch = g & 3;
            uint32_t d = SWZ64((uint32_t)(row * 64 + ch * 16));
            cpa16(base + 8192 + d, Bh + (size_t)(n0 + row) * K + k0 + ch * 8);
        }
        CPA_COMMIT();
    };

    const int NCH = K / KC;
    load_chunk(0, 0);
    load_chunk(1, 1);
    load_chunk(2, 2);

    int quad = lane >> 3, lr = lane & 7;
    int a_row = lr + (quad & 1) * 8;
    int a_chd = quad >> 1;
    int b_row = (quad >> 1) * 8 + lr;
    int b_chd = quad & 1;

    for (int c = 0; c < NCH; c++){
        int s = c & 3;
        if (c >= NCH - 3) asm volatile("cp.async.wait_group 0;" ::: "memory");
        else              asm volatile("cp.async.wait_group 2;" ::: "memory");
        __syncthreads();
        if (c + 3 < NCH) load_chunk(c + 3, (c + 3) & 3);

        uint32_t base = sb + s * STG1;
        #pragma unroll
        for (int kk = 0; kk < 2; kk++){
            uint32_t ah[4][4];
            #pragma unroll
            for (int mi = 0; mi < 4; mi++){
                int row = warp_m + mi * 16 + a_row;
                int ch  = kk * 2 + a_chd;
                ldsm4(ah[mi][0], ah[mi][1], ah[mi][2], ah[mi][3],
                      base + SWZ64((uint32_t)(row * 64 + ch * 16)));
            }
            uint32_t bh[8][2];
            #pragma unroll
            for (int p = 0; p < 4; p++){
                int row = warp_n + p * 16 + b_row;
                int ch  = kk * 2 + b_chd;
                ldsm4(bh[p*2][0], bh[p*2][1], bh[p*2+1][0], bh[p*2+1][1],
                      base + 8192 + SWZ64((uint32_t)(row * 64 + ch * 16)));
            }
            #pragma unroll
            for (int mi = 0; mi < 4; mi++)
                #pragma unroll
                for (int nj = 0; nj < 8; nj++)
                    mmah(acc[mi][nj], ah[mi][0], ah[mi][1], ah[mi][2], ah[mi][3],
                         bh[nj][0], bh[nj][1]);
        }
        __syncthreads();
    }

    #pragma unroll
    for (int mi = 0; mi < 4; mi++){
        int rrow = m0 + warp_m + mi * 16 + (lane >> 2);
        #pragma unroll
        for (int nj = 0; nj < 8; nj++){
            int ccol = n0 + warp_n + nj * 8 + (lane & 3) * 2;
            float b0 = bias[ccol], b1 = bias[ccol + 1];
            float2 v0; v0.x = acc[mi][nj][0] + b0; v0.y = acc[mi][nj][1] + b1;
            float2 v1; v1.x = acc[mi][nj][2] + b0; v1.y = acc[mi][nj][3] + b1;
            *(float2*)(C + (size_t)rrow * N + ccol) = v0;
            *(float2*)(C + (size_t)(rrow + 8) * N + ccol) = v1;
        }
    }
}

// ---------------- persistent MMA sLSTM recurrence -----------------------------
#define W0OFF 0
#define W1OFF 65536
#define W2OFF 131072
#define BUFA  196608
#define BUFB  212992
#define RNN_SMEM 229376

// padded flag-array barrier: one 128B line per flag, 32-lane distributed poll
__device__ __forceinline__ void gridbar(int k){
    __syncthreads();
    unsigned tgt = (unsigned)k + 1u;
    if (threadIdx.x == 0)
        asm volatile("st.release.gpu.global.u32 [%0], %1;"
                     :: "l"(g_flags + blockIdx.x * 32), "r"(tgt) : "memory");
    if (threadIdx.x < 32){
        const unsigned* f = g_flags + threadIdx.x * 32;
        bool ok;
        do {
            unsigned v0, v1, v2, v3;
            asm volatile("ld.relaxed.gpu.global.u32 %0, [%1];" : "=r"(v0) : "l"(f)        : "memory");
            asm volatile("ld.relaxed.gpu.global.u32 %0, [%1];" : "=r"(v1) : "l"(f + 1024) : "memory");
            asm volatile("ld.relaxed.gpu.global.u32 %0, [%1];" : "=r"(v2) : "l"(f + 2048) : "memory");
            asm volatile("ld.relaxed.gpu.global.u32 %0, [%1];" : "=r"(v3) : "l"(f + 3072) : "memory");
            ok = (v0 >= tgt) && (v1 >= tgt) && (v2 >= tgt) && (v3 >= tgt);
        } while (!__all_sync(0xffffffffu, ok));
        __threadfence();
    }
    __syncthreads();
}

__global__ void __launch_bounds__(256, 1)
rnn_kernel(const float* __restrict__ Whh0, const float* __restrict__ Wih1,
           const float* __restrict__ Whh1, const float* __restrict__ bg1){
    extern __shared__ __align__(1024) unsigned char sm[];
    uint32_t sb = smem_u32(sm);
    float* gsc1 = (float*)(sm + BUFA);          // [64][16], overlays BUFA
    float* gsc2 = (float*)(sm + BUFA + 4096);   // [2][32][16]
    int tid = threadIdx.x, w = tid >> 5, lane = tid & 31;
    int j0 = blockIdx.x * 8;

    {
        const float* mats[3] = { Whh0, Wih1, Whh1 };
        for (int c = tid; c < 3 * 32 * 128; c += 256){
            int mat = c >> 12, cm = c & 4095;
            int r = cm >> 7, ch = cm & 127;
            int g = r >> 3, jj = r & 7;
            const float* src = mats[mat] + (size_t)(g * Hdim + j0 + jj) * Hdim + ch * 8;
            float4 v0 = *(const float4*)src;
            float4 v1 = *(const float4*)(src + 4);
            uint4 pk;
            pk.x = pkh(v0.x, v0.y); pk.y = pkh(v0.z, v0.w);
            pk.z = pkh(v1.x, v1.y); pk.w = pkh(v1.z, v1.w);
            *(uint4*)(sm + mat * 65536 + r * 2048 + (uint32_t)((ch ^ (r & 7)) << 4)) = pk;
        }
    }
    int jl = tid & 7, bbt = (tid >> 3) & 15, jg = j0 + jl;
    bool upd = tid < 128;
    float bg0 = 0, bg1v = 0, bg2 = 0, bg3 = 0;
    if (upd){
        bg0  = bg1[0 * Hdim + jg];
        bg1v = bg1[1 * Hdim + jg];
        bg2  = bg1[2 * Hdim + jg];
        bg3  = bg1[3 * Hdim + jg];
    }
    __syncthreads();

    int quad = lane >> 3, lr = lane & 7;
    int ar  = lr + (quad & 1) * 8;
    int ak8 = quad >> 1;
    int ar7 = ar & 7;
    int br  = lr;
    int bk8 = (lane >> 3) & 1;
    uint32_t wb1 = sb + ((w < 4) ? (uint32_t)(W0OFF + w * 8 * 2048)
                                 : (uint32_t)(W1OFF + (w - 4) * 8 * 2048)) + br * 2048;
    uint32_t wb2 = sb + W2OFF + (w & 3) * 8 * 2048 + br * 2048;
    int mb = lane >> 2, nn = (lane & 3) * 2;

    auto stage = [&](uint32_t buf, const char* hsrc, int hf){
        #pragma unroll
        for (int i = 0; i < 4; i++){
            int c = tid + i * 256;
            int b = c >> 6, ch = c & 63;
            cpa16(sb + buf + b * 1024 + (uint32_t)((ch ^ (b & 7)) << 4),
                  hsrc + b * 2048 + hf * 1024 + ch * 16);
        }
        CPA_COMMIT();
    };
    auto sweep1 = [&](uint32_t buf, int hf, float* a1){
        uint32_t ab = sb + buf + ar * 1024;
        #pragma unroll 8
        for (int ks = 0; ks < 32; ks++){
            uint32_t x0, x1, x2, x3, y0, y1;
            ldsm4(x0, x1, x2, x3, ab + (uint32_t)((((ks << 1) + ak8) ^ ar7) << 4));
            int kg = (hf << 5) + ks;
            ldsm2(y0, y1, wb1 + (uint32_t)((((kg << 1) + bk8) ^ br) << 4));
            mmah(a1, x0, x1, x2, x3, y0, y1);
        }
    };
    auto sweep2 = [&](uint32_t buf, int hf, float* a2){
        uint32_t ab = sb + buf + ar * 1024;
        int ks0 = (w >> 2) << 4;
        #pragma unroll 8
        for (int q = 0; q < 16; q++){
            int ks = ks0 + q;
            uint32_t x0, x1, x2, x3, y0, y1;
            ldsm4(x0, x1, x2, x3, ab + (uint32_t)((((ks << 1) + ak8) ^ ar7) << 4));
            int kg = (hf << 5) + ks;
            ldsm2(y0, y1, wb2 + (uint32_t)((((kg << 1) + bk8) ^ br) << 4));
            mmah(a2, x0, x1, x2, x3, y0, y1);
        }
    };

    float c0 = 0.0f, c1 = 0.0f;

    for (int k = 0; k <= Sdim; k++){
        float ihv0 = 0, ihv1 = 0, ihv2 = 0, ihv3 = 0;
        if (upd && k < Sdim){
            const float* ih = g_ih0 + (size_t)(bbt * Sdim + k) * G4H + jg;
            ihv0 = __ldg(ih);
            ihv1 = __ldg(ih + Hdim);
            ihv2 = __ldg(ih + 2 * Hdim);
            ihv3 = __ldg(ih + 3 * Hdim);
        }

        if (k >= 1){
            const char* h0src = (const char*)g_h0[(k - 1) & 1];
            const char* h1src = (const char*)g_h1[k & 1];
            float a1[4] = {0, 0, 0, 0}, a2[4] = {0, 0, 0, 0};

            stage(BUFA, h0src, 0);
            stage(BUFB, h0src, 1);
            asm volatile("cp.async.wait_group 1;" ::: "memory");
            __syncthreads();
            sweep1(BUFA, 0, a1);
            __syncthreads();
            stage(BUFA, h1src, 0);
            asm volatile("cp.async.wait_group 1;" ::: "memory");
            __syncthreads();
            sweep1(BUFB, 1, a1);
            __syncthreads();
            stage(BUFB, h1src, 1);
            asm volatile("cp.async.wait_group 1;" ::: "memory");
            __syncthreads();
            sweep2(BUFA, 0, a2);
            asm volatile("cp.async.wait_group 0;" ::: "memory");
            __syncthreads();               // BUFB visible + all BUFA reads done
            sweep2(BUFB, 1, a2);

            gsc1[(8 * w + nn) * 16 + mb]         = a1[0];
            gsc1[(8 * w + nn + 1) * 16 + mb]     = a1[1];
            gsc1[(8 * w + nn) * 16 + mb + 8]     = a1[2];
            gsc1[(8 * w + nn + 1) * 16 + mb + 8] = a1[3];
            float* g2 = gsc2 + (w >> 2) * 512;
            g2[(8 * (w & 3) + nn) * 16 + mb]         = a2[0];
            g2[(8 * (w & 3) + nn + 1) * 16 + mb]     = a2[1];
            g2[(8 * (w & 3) + nn) * 16 + mb + 8]     = a2[2];
            g2[(8 * (w & 3) + nn + 1) * 16 + mb + 8] = a2[3];
        }
        __syncthreads();

        if (upd){
            if (k < Sdim){
                float r0 = 0, r1 = 0, r2 = 0, r3 = 0;
                if (k >= 1){
                    r0 = gsc1[jl * 16 + bbt];
                    r1 = gsc1[(8 + jl) * 16 + bbt];
                    r2 = gsc1[(16 + jl) * 16 + bbt];
                    r3 = gsc1[(24 + jl) * 16 + bbt];
                }
                float gi = r0 + ihv0, gf = r1 + ihv1, gz = r2 + ihv2, go = r3 + ihv3;
                float cn = sigmoidf_(gf) * c0 + expf(gi) * tanhf(gz);
                float hn = sigmoidf_(go) * tanhf(cn);
                c0 = cn;
                g_h0[k & 1][bbt][jg] = __float2half_rn(hn);
            }
            if (k >= 1){
                float gi = gsc1[(32 + jl) * 16 + bbt] + gsc2[jl * 16 + bbt]
                         + gsc2[512 + jl * 16 + bbt] + bg0;
                float gf = gsc1[(40 + jl) * 16 + bbt] + gsc2[(8 + jl) * 16 + bbt]
                         + gsc2[512 + (8 + jl) * 16 + bbt] + bg1v;
                float gz = gsc1[(48 + jl) * 16 + bbt] + gsc2[(16 + jl) * 16 + bbt]
                         + gsc2[512 + (16 + jl) * 16 + bbt] + bg2;
                float go = gsc1[(56 + jl) * 16 + bbt] + gsc2[(24 + jl) * 16 + bbt]
                         + gsc2[512 + (24 + jl) * 16 + bbt] + bg3;
                float cn = sigmoidf_(gf) * c1 + expf(gi) * tanhf(gz);
                float hn = sigmoidf_(go) * tanhf(cn);
                c1 = cn;
                g_h1[(k - 1) & 1][bbt][jg] = __float2half_rn(hn);
                g_ah[((size_t)bbt * Sdim + (k - 1)) * Hdim + jg] = __float2half_rn(hn);
            }
        }
        if (k < Sdim) gridbar(k);
    }
}

// ---------------- GELU + residual + LayerNorm (emits fp32 + fp16) -------------
__global__ void __launch_bounds__(256)
post_kernel(const float* __restrict__ lng, const float* __restrict__ lnb){
    __shared__ float red[8];
    __shared__ float s_stat;
    int tok = blockIdx.x, tid = threadIdx.x;
    int lane = tid & 31, wid = tid >> 5;
    const float* pr = g_proj + (size_t)tok * Hdim;
    float* xr = g_x + (size_t)tok * Hdim;
    __half* hr = g_ah + (size_t)tok * Hdim;

    float yv[4];
    float lsum = 0.0f;
    #pragma unroll
    for (int i = 0; i < 4; i++){
        int e = tid + i * 256;
        float v = pr[e];
        float gl = 0.5f * v * (1.0f + erff(v * 0.70710678118654752440f));
        float y = gl + xr[e];
        yv[i] = y;
        lsum += y;
    }
    #pragma unroll
    for (int off = 16; off; off >>= 1) lsum += __shfl_xor_sync(0xffffffffu, lsum, off);
    if (lane == 0) red[wid] = lsum;
    __syncthreads();
    if (wid == 0){
        float ts = (lane < 8) ? red[lane] : 0.0f;
        #pragma unroll
        for (int off = 4; off; off >>= 1) ts += __shfl_xor_sync(0xffffffffu, ts, off);
        if (lane == 0) s_stat = ts * (1.0f / Hdim);
    }
    __syncthreads();
    float mean = s_stat;
    __syncthreads();

    float lss = 0.0f;
    #pragma unroll
    for (int i = 0; i < 4; i++){ float d = yv[i] - mean; lss += d * d; }
    #pragma unroll
    for (int off = 16; off; off >>= 1) lss += __shfl_xor_sync(0xffffffffu, lss, off);
    if (lane == 0) red[wid] = lss;
    __syncthreads();
    if (wid == 0){
        float ts = (lane < 8) ? red[lane] : 0.0f;
        #pragma unroll
        for (int off = 4; off; off >>= 1) ts += __shfl_xor_sync(0xffffffffu, ts, off);
        if (lane == 0) s_stat = rsqrtf(ts * (1.0f / Hdim) + 1e-5f);
    }
    __syncthreads();
    float inv = s_stat;

    #pragma unroll
    for (int i = 0; i < 4; i++){
        int e = tid + i * 256;
        float o = (yv[i] - mean) * inv * lng[e] + lnb[e];
        xr[e] = o;
        hr[e] = __float2half_rn(o);
    }
}

// ---------------- driver -------------------------------------------------------
extern "C" void kernel_launch(void* const* d_in, const int* in_sizes, int n_in,
                              void* d_out, int out_size){
    const int*   seq = (const int*)  d_in[0];
    const float* emb = (const float*)d_in[1];
    const float* Wih = (const float*)d_in[2];
    const float* Whh = (const float*)d_in[3];
    const float* bg  = (const float*)d_in[4];
    const float* pW  = (const float*)d_in[5];
    const float* pb  = (const float*)d_in[6];
    const float* lng = (const float*)d_in[7];
    const float* lnb = (const float*)d_in[8];
    const float* oW  = (const float*)d_in[9];
    const float* ob  = (const float*)d_in[10];
    float* out = (float*)d_out;

    cudaFuncSetAttribute(rnn_kernel, cudaFuncAttributeMaxDynamicSharedMemorySize, RNN_SMEM);
    cudaFuncSetAttribute(gemm_tc1, cudaFuncAttributeMaxDynamicSharedMemorySize, GEMM1_SMEM);

    float *px, *pih, *pproj;
    __half *pah, *pbh;
    cudaGetSymbolAddress((void**)&px,    g_x);
    cudaGetSymbolAddress((void**)&pih,   g_ih0);
    cudaGetSymbolAddress((void**)&pproj, g_proj);
    cudaGetSymbolAddress((void**)&pah,   g_ah);
    cudaGetSymbolAddress((void**)&pbh,   g_bh);

    embed_kernel<<<NTOK, 256>>>(seq, emb);

    for (int blk = 0; blk < 2; blk++){
        const float* Wih_b = Wih + (size_t)blk * 2 * G4H * Hdim;
        const float* Whh_b = Whh + (size_t)blk * 2 * G4H * Hdim;
        const float* bg_b  = bg  + blk * 2 * G4H;

        // ih0 = x @ Wih0^T + bg0, single-pass fp16, m-major grid
        half_kernel<<<2048, 256>>>(Wih_b, pbh, (size_t)G4H * Hdim / 4);
        {
            dim3 g(NTOK / 128, G4H / 256);
            gemm_tc1<<<g, 256, GEMM1_SMEM>>>(pah, pbh, bg_b, pih, G4H);
        }

        init_kernel<<<64, 256>>>();
        rnn_kernel<<<RNN_BLOCKS, 256, RNN_SMEM>>>(
            Whh_b, Wih_b + (size_t)G4H * Hdim, Whh_b + (size_t)G4H * Hdim, bg_b + G4H);

        // proj = seq @ pW^T + pb, single-pass fp16
        half_kernel<<<2048, 256>>>(pW + (size_t)blk * Hdim * Hdim, pbh,
                                   (size_t)Hdim * Hdim / 4);
        {
            dim3 g(NTOK / 128, Hdim / 256);
            gemm_tc1<<<g, 256, GEMM1_SMEM>>>(pah, pbh, pb + blk * Hdim, pproj, Hdim);
        }
        post_kernel<<<NTOK, 256>>>(lng + blk * Hdim, lnb + blk * Hdim);
    }

    // logits = x @ oW^T + ob, single-pass fp16, m-major grid (B L2-streamed once)
    half_kernel<<<2048, 256>>>(oW, pbh, (size_t)Vdim * Hdim / 4);
    {
        dim3 g(NTOK / 128, Vdim / 256);
        gemm_tc1<<<g, 256, GEMM1_SMEM>>>(pah, pbh, ob, out, Vdim);
    }
}